// round 16
// baseline (speedup 1.0000x reference)
#include <cuda_runtime.h>
#include <cuda_fp16.h>
#include <cstdint>

// Problem constants
#define S_LEN  2048
#define BATCH  2
#define NHEAD  16
#define HDIM   64
#define HID    1024
#define M_TOT  (BATCH * S_LEN)   // 4096

// Q pre-scale: 1/sqrt(64) * log2(e)  (softmax runs in exp2 domain)
#define QSCALE 0.18033688011112042f

// ---------------------------------------------------------------------------
// Scratch (allocation-free contract: __device__ globals), fp16
// ---------------------------------------------------------------------------
__device__ __align__(16) __half g_xhi[M_TOT * HID];
__device__ __align__(16) __half g_whi[4 * HID * HID];   // wq|wk|wv|wo
__device__ __align__(16) __half g_qhi[M_TOT * HID];     // [b][h][s][d]
__device__ __align__(16) __half g_khi[M_TOT * HID];
__device__ __align__(16) __half g_vhi[M_TOT * HID];
__device__ __align__(16) __half g_ohi[M_TOT * HID];     // [b][s][h*64+d]

// ---------------------------------------------------------------------------
// PTX helpers (plain-sm_103-legal: ldmatrix / mma.sync / cp.async)
// ---------------------------------------------------------------------------
__device__ __forceinline__ uint32_t smem_u32(const void* p) {
    uint32_t a;
    asm("{ .reg .u64 t; cvta.to.shared.u64 t, %1; cvt.u32.u64 %0, t; }" : "=r"(a) : "l"(p));
    return a;
}

#define CP16(dst, src) \
    asm volatile("cp.async.cg.shared.global [%0], [%1], 16;" :: "r"(dst), "l"(src))
__device__ __forceinline__ void cp_commit() { asm volatile("cp.async.commit_group;" ::: "memory"); }
__device__ __forceinline__ void cp_wait0()  { asm volatile("cp.async.wait_group 0;" ::: "memory"); }
__device__ __forceinline__ void cp_wait1()  { asm volatile("cp.async.wait_group 1;" ::: "memory"); }

#define LDSM4(r, addr) \
    asm volatile("ldmatrix.sync.aligned.m8n8.x4.shared.b16 {%0,%1,%2,%3}, [%4];" \
        : "=r"((r)[0]), "=r"((r)[1]), "=r"((r)[2]), "=r"((r)[3]) : "r"(addr))
#define LDSM4T(r, addr) \
    asm volatile("ldmatrix.sync.aligned.m8n8.x4.trans.shared.b16 {%0,%1,%2,%3}, [%4];" \
        : "=r"((r)[0]), "=r"((r)[1]), "=r"((r)[2]), "=r"((r)[3]) : "r"(addr))

#define MMA(d, a, b0_, b1_) \
    asm volatile("mma.sync.aligned.m16n8k16.row.col.f32.f16.f16.f32 " \
        "{%0,%1,%2,%3}, {%4,%5,%6,%7}, {%8,%9}, {%0,%1,%2,%3};" \
        : "+f"((d)[0]), "+f"((d)[1]), "+f"((d)[2]), "+f"((d)[3]) \
        : "r"((a)[0]), "r"((a)[1]), "r"((a)[2]), "r"((a)[3]), "r"(b0_), "r"(b1_))

#define EX2(d, x) asm("ex2.approx.f32 %0, %1;" : "=f"(d) : "f"(x))

__device__ __forceinline__ uint32_t packh2(__half a, __half b) {
    __half2 t = __halves2half2(a, b);
    return *reinterpret_cast<uint32_t*>(&t);
}

// ---------------------------------------------------------------------------
// fp32 -> fp16 convert kernels
// ---------------------------------------------------------------------------
__global__ __launch_bounds__(256)
void conv_h(const float4* __restrict__ x, uint32_t* __restrict__ hi, int n4)
{
    int i = blockIdx.x * 256 + threadIdx.x;
    if (i >= n4) return;
    float4 v = x[i];
    hi[i * 2 + 0] = packh2(__float2half_rn(v.x), __float2half_rn(v.y));
    hi[i * 2 + 1] = packh2(__float2half_rn(v.z), __float2half_rn(v.w));
}

__global__ __launch_bounds__(256)
void conv_w4(const float4* __restrict__ w0, const float4* __restrict__ w1,
             const float4* __restrict__ w2, const float4* __restrict__ w3,
             uint32_t* __restrict__ hi)
{
    const int z = blockIdx.y;
    const int n4 = HID * HID / 4;
    int i = blockIdx.x * 256 + threadIdx.x;
    if (i >= n4) return;
    const float4* src = (z == 0) ? w0 : (z == 1) ? w1 : (z == 2) ? w2 : w3;
    float4 v = src[i];
    uint32_t* H = hi + (size_t)z * (HID * HID / 2);
    H[i * 2 + 0] = packh2(__float2half_rn(v.x), __float2half_rn(v.y));
    H[i * 2 + 1] = packh2(__float2half_rn(v.z), __float2half_rn(v.w));
}

// ---------------------------------------------------------------------------
// fp16 1-pass GEMM via mma.sync (unchanged from R15 except Q scale constant)
// ---------------------------------------------------------------------------
#define G_ARR   10240
#define G_STAGE (2 * G_ARR)
#define GEMM_SMEM (2 * G_STAGE)

template <int MODE>
__global__ __launch_bounds__(256)
void gemm_h(const __half* __restrict__ Ahi, const __half* __restrict__ Wh,
            const float* __restrict__ bias0, const float* __restrict__ bias1,
            const float* __restrict__ bias2,
            __half* o0h, __half* o1h, __half* o2h, float* outF)
{
    extern __shared__ __align__(16) char smem[];
    const uint32_t sb = smem_u32(smem);
    const int tid = threadIdx.x;
    const int lane = tid & 31;
    const int wid = tid >> 5;
    const int wm = wid & 1;
    const int wn = wid >> 1;
    const int gid = lane >> 2;
    const int tig = lane & 3;
    const int m0 = blockIdx.y * 128;
    const int n0 = blockIdx.x * 128;
    const int z = (MODE == 0) ? blockIdx.z : 0;

    const uint4* pA0 = (const uint4*)Ahi + (size_t)m0 * 128;
    const uint4* pB0 = (const uint4*)(Wh + (size_t)z * HID * HID) + (size_t)n0 * 128;

    float acc[4][4][4];
#pragma unroll
    for (int mt = 0; mt < 4; mt++)
#pragma unroll
        for (int nt = 0; nt < 4; nt++)
#pragma unroll
            for (int e = 0; e < 4; e++) acc[mt][nt][e] = 0.f;

    auto load_stage = [&](int st, int ck) {
        const uint32_t dbase = sb + st * G_STAGE;
#pragma unroll
        for (int a = 0; a < 2; a++) {
            const uint4* src = (a == 0) ? pA0 : pB0;
#pragma unroll
            for (int i = 0; i < 2; i++) {
                int idx = tid + i * 256;
                int row = idx >> 2, q = idx & 3;
                uint32_t dst = dbase + a * G_ARR + row * 80 + q * 16;
                CP16(dst, src + (size_t)row * 128 + ck * 4 + q);
            }
        }
    };

    load_stage(0, 0);
    cp_commit();

    for (int ck = 0; ck < HID / 32; ck++) {
        if (ck + 1 < HID / 32) { load_stage((ck + 1) & 1, ck + 1); cp_commit(); cp_wait1(); }
        else cp_wait0();
        __syncthreads();

        const uint32_t sA = sb + (ck & 1) * G_STAGE;
        const uint32_t sB = sA + G_ARR;

#pragma unroll
        for (int ks = 0; ks < 2; ks++) {
            uint32_t ah[4][4];
#pragma unroll
            for (int mt = 0; mt < 4; mt++) {
                uint32_t off = (uint32_t)((wm * 64 + mt * 16 + (lane & 15)) * 80
                                          + (ks * 16 + (lane >> 4) * 8) * 2);
                LDSM4(ah[mt], sA + off);
            }
            uint32_t bh[4][2];
#pragma unroll
            for (int np = 0; np < 2; np++) {
                uint32_t rB = wn * 32 + np * 16 + (lane & 7) + ((lane >> 4) << 3);
                uint32_t cB = ks * 16 + ((lane >> 3) & 1) * 8;
                uint32_t off = rB * 80 + cB * 2;
                uint32_t t0[4];
                LDSM4(t0, sB + off);
                bh[2*np][0] = t0[0]; bh[2*np][1] = t0[1];
                bh[2*np+1][0] = t0[2]; bh[2*np+1][1] = t0[3];
            }
#pragma unroll
            for (int mt = 0; mt < 4; mt++)
#pragma unroll
                for (int nt = 0; nt < 4; nt++)
                    MMA(acc[mt][nt], ah[mt], bh[nt][0], bh[nt][1]);
        }
        __syncthreads();
    }

    const float* bias = (MODE == 1) ? bias0 : (z == 0 ? bias0 : (z == 1 ? bias1 : bias2));
    const float scale = (MODE == 0 && z == 0) ? QSCALE : 1.0f;

#pragma unroll
    for (int mt = 0; mt < 4; mt++) {
#pragma unroll
        for (int nt = 0; nt < 4; nt++) {
            const int m_lo = m0 + wm * 64 + mt * 16 + gid;
            const int m_hi = m_lo + 8;
            const int n = n0 + wn * 32 + nt * 8 + 2 * tig;
            const float b0v = bias[n], b1v = bias[n + 1];
            float v0 = (acc[mt][nt][0] + b0v) * scale;
            float v1 = (acc[mt][nt][1] + b1v) * scale;
            float v2 = (acc[mt][nt][2] + b0v) * scale;
            float v3 = (acc[mt][nt][3] + b1v) * scale;
            if (MODE == 0) {
                const int hh = n >> 6, d = n & 63;
                const size_t base0 = (((size_t)((m_lo >> 11) * NHEAD + hh) * S_LEN) + (m_lo & 2047)) * 64 + d;
                const size_t base1 = (((size_t)((m_hi >> 11) * NHEAD + hh) * S_LEN) + (m_hi & 2047)) * 64 + d;
                __half* oH = (z == 0) ? o0h : (z == 1 ? o1h : o2h);
                *(uint32_t*)(oH + base0) = packh2(__float2half_rn(v0), __float2half_rn(v1));
                *(uint32_t*)(oH + base1) = packh2(__float2half_rn(v2), __float2half_rn(v3));
            } else {
                *(float2*)(outF + (size_t)m_lo * HID + n) = make_float2(v0, v1);
                *(float2*)(outF + (size_t)m_hi * HID + n) = make_float2(v2, v3);
            }
        }
    }
}

// ---------------------------------------------------------------------------
// Flash attention (causal), mma.sync, fp16, exp2-domain softmax.
// Br=128: 4 warps, each warp owns m32 (2 m16 frags) -> K/V ldmatrix reuse x2.
// Bc=64. grid: (S/128, NHEAD, BATCH), x reversed (heavy first).
// Warp-level skip of fully-masked diagonal tiles.
// smem: 2 stages x (K,V) x 64 rows x 144 B = 36864 B.
// ---------------------------------------------------------------------------
#define F_ARR   9216
#define F_STAGE (2 * F_ARR)
#define FLASH_SMEM (2 * F_STAGE)

__global__ __launch_bounds__(128)
void flash_mma(const __half* __restrict__ Qhi,
               const __half* __restrict__ Khi,
               const __half* __restrict__ Vhi,
               __half* __restrict__ Ohi)
{
    extern __shared__ __align__(16) char smem[];
    const uint32_t sb = smem_u32(smem);
    const int tid = threadIdx.x;
    const int lane = tid & 31;
    const int w = tid >> 5;
    const int gid = lane >> 2;
    const int tig = lane & 3;

    const int qx = (S_LEN / 128 - 1) - blockIdx.x;   // heavy blocks first
    const int q0 = qx * 128;
    const int h = blockIdx.y, b = blockIdx.z;
    const int bh = b * NHEAD + h;
    const size_t hoff = (size_t)bh * S_LEN * HDIM;

    const __half* Qh = Qhi + hoff;
    const uint4* K0 = (const uint4*)(Khi + hoff);
    const uint4* V0 = (const uint4*)(Vhi + hoff);

    // warp rows: q0 + w*32 + mf*16 + gid (+8)
    const int wrow = q0 + w * 32;
    uint32_t qh[2][4][4];
#pragma unroll
    for (int mf = 0; mf < 2; mf++) {
        const int r = wrow + mf * 16 + gid;
#pragma unroll
        for (int kt = 0; kt < 4; kt++) {
            const int c = kt * 16 + 2 * tig;
            qh[mf][kt][0] = *(const uint32_t*)(Qh + (size_t)r * 64 + c);
            qh[mf][kt][1] = *(const uint32_t*)(Qh + (size_t)(r + 8) * 64 + c);
            qh[mf][kt][2] = *(const uint32_t*)(Qh + (size_t)r * 64 + c + 8);
            qh[mf][kt][3] = *(const uint32_t*)(Qh + (size_t)(r + 8) * 64 + c + 8);
        }
    }

    float oa[2][8][4];
#pragma unroll
    for (int mf = 0; mf < 2; mf++)
#pragma unroll
        for (int j = 0; j < 8; j++)
#pragma unroll
            for (int e = 0; e < 4; e++) oa[mf][j][e] = 0.f;
    float mrow[2][2] = {{-INFINITY, -INFINITY}, {-INFINITY, -INFINITY}};
    float lrow[2][2] = {{0.f, 0.f}, {0.f, 0.f}};

    const int ntile = 2 * qx + 2;
    auto load_kv = [&](int st, int t) {
        const int c0 = t * 64;
        const uint32_t dbase = sb + st * F_STAGE;
#pragma unroll
        for (int a = 0; a < 2; a++) {
            const uint4* src = (a == 0) ? K0 : V0;
#pragma unroll
            for (int i = 0; i < 4; i++) {
                int idx = tid + i * 128;
                int row = idx >> 3, q = idx & 7;
                uint32_t dst = dbase + a * F_ARR + row * 144 + q * 16;
                CP16(dst, src + (size_t)(c0 + row) * 8 + q);
            }
        }
    };

    load_kv(0, 0);
    cp_commit();

    for (int t = 0; t < ntile; t++) {
        if (t + 1 < ntile) { load_kv((t + 1) & 1, t + 1); cp_commit(); cp_wait1(); }
        else cp_wait0();
        __syncthreads();

        // warp-level causal skip: tile fully above diagonal for this warp
        const bool active = (t * 64 <= wrow + 31);
        if (active) {
            const uint32_t kb = sb + (t & 1) * F_STAGE;
            const uint32_t vb = kb + F_ARR;

            // ---- S = Q K^T  (K frags shared by both M-frags)
            float sc[2][8][4];
#pragma unroll
            for (int mf = 0; mf < 2; mf++)
#pragma unroll
                for (int j = 0; j < 8; j++)
#pragma unroll
                    for (int e = 0; e < 4; e++) sc[mf][j][e] = 0.f;

#pragma unroll
            for (int kt = 0; kt < 4; kt++) {
#pragma unroll
                for (int np = 0; np < 4; np++) {
                    uint32_t rB = np * 16 + (lane & 7) + ((lane >> 4) << 3);
                    uint32_t cB = kt * 16 + ((lane >> 3) & 1) * 8;
                    uint32_t off = rB * 144 + cB * 2;
                    uint32_t t0[4];
                    LDSM4(t0, kb + off);
#pragma unroll
                    for (int mf = 0; mf < 2; mf++) {
                        MMA(sc[mf][2*np],   qh[mf][kt], t0[0], t0[1]);
                        MMA(sc[mf][2*np+1], qh[mf][kt], t0[2], t0[3]);
                    }
                }
            }

            // ---- causal mask (only the two diagonal-adjacent tiles)
            if (t >= ntile - 2) {
#pragma unroll
                for (int mf = 0; mf < 2; mf++) {
                    const int r0 = wrow + mf * 16 + gid;
                    const int r1 = r0 + 8;
#pragma unroll
                    for (int j = 0; j < 8; j++) {
                        const int c = t * 64 + 8 * j + 2 * tig;
                        if (c > r0)     sc[mf][j][0] = -INFINITY;
                        if (c + 1 > r0) sc[mf][j][1] = -INFINITY;
                        if (c > r1)     sc[mf][j][2] = -INFINITY;
                        if (c + 1 > r1) sc[mf][j][3] = -INFINITY;
                    }
                }
            }

            // ---- online softmax (exp2 domain; rescale only on max change)
            uint32_t ph[2][4][4];
#pragma unroll
            for (int mf = 0; mf < 2; mf++) {
                float mxl = -INFINITY, mxh = -INFINITY;
#pragma unroll
                for (int j = 0; j < 8; j++) {
                    mxl = fmaxf(mxl, fmaxf(sc[mf][j][0], sc[mf][j][1]));
                    mxh = fmaxf(mxh, fmaxf(sc[mf][j][2], sc[mf][j][3]));
                }
                mxl = fmaxf(mxl, __shfl_xor_sync(0xffffffffu, mxl, 1));
                mxl = fmaxf(mxl, __shfl_xor_sync(0xffffffffu, mxl, 2));
                mxh = fmaxf(mxh, __shfl_xor_sync(0xffffffffu, mxh, 1));
                mxh = fmaxf(mxh, __shfl_xor_sync(0xffffffffu, mxh, 2));

                if (mxl > mrow[mf][0] || mxh > mrow[mf][1]) {
                    const float mnl = fmaxf(mrow[mf][0], mxl);
                    const float mnh = fmaxf(mrow[mf][1], mxh);
                    float cl, ch;
                    EX2(cl, mrow[mf][0] - mnl);
                    EX2(ch, mrow[mf][1] - mnh);
                    lrow[mf][0] *= cl; lrow[mf][1] *= ch;
                    mrow[mf][0] = mnl; mrow[mf][1] = mnh;
#pragma unroll
                    for (int j = 0; j < 8; j++) {
                        oa[mf][j][0] *= cl; oa[mf][j][1] *= cl;
                        oa[mf][j][2] *= ch; oa[mf][j][3] *= ch;
                    }
                }

                float rsl = 0.f, rsh = 0.f;
#pragma unroll
                for (int j = 0; j < 8; j++) {
                    EX2(sc[mf][j][0], sc[mf][j][0] - mrow[mf][0]);
                    EX2(sc[mf][j][1], sc[mf][j][1] - mrow[mf][0]);
                    EX2(sc[mf][j][2], sc[mf][j][2] - mrow[mf][1]);
                    EX2(sc[mf][j][3], sc[mf][j][3] - mrow[mf][1]);
                    rsl += sc[mf][j][0] + sc[mf][j][1];
                    rsh += sc[mf][j][2] + sc[mf][j][3];
                }
                rsl += __shfl_xor_sync(0xffffffffu, rsl, 1);
                rsl += __shfl_xor_sync(0xffffffffu, rsl, 2);
                rsh += __shfl_xor_sync(0xffffffffu, rsh, 1);
                rsh += __shfl_xor_sync(0xffffffffu, rsh, 2);
                lrow[mf][0] += rsl; lrow[mf][1] += rsh;

#pragma unroll
                for (int kt = 0; kt < 4; kt++) {
                    const int j0 = 2 * kt, j1 = 2 * kt + 1;
                    ph[mf][kt][0] = packh2(__float2half_rn(sc[mf][j0][0]), __float2half_rn(sc[mf][j0][1]));
                    ph[mf][kt][1] = packh2(__float2half_rn(sc[mf][j0][2]), __float2half_rn(sc[mf][j0][3]));
                    ph[mf][kt][2] = packh2(__float2half_rn(sc[mf][j1][0]), __float2half_rn(sc[mf][j1][1]));
                    ph[mf][kt][3] = packh2(__float2half_rn(sc[mf][j1][2]), __float2half_rn(sc[mf][j1][3]));
                }
            }

            // ---- O += P V  (V frags shared by both M-frags)
#pragma unroll
            for (int kt = 0; kt < 4; kt++) {
#pragma unroll
                for (int dp = 0; dp < 4; dp++) {
                    uint32_t rV = kt * 16 + (lane & 7) + (((lane >> 3) & 1) << 3);
                    uint32_t cV = dp * 16 + ((lane >> 4) << 3);
                    uint32_t off = rV * 144 + cV * 2;
                    uint32_t v0[4];
                    LDSM4T(v0, vb + off);
#pragma unroll
                    for (int mf = 0; mf < 2; mf++) {
                        MMA(oa[mf][2*dp],   ph[mf][kt], v0[0], v0[1]);
                        MMA(oa[mf][2*dp+1], ph[mf][kt], v0[2], v0[3]);
                    }
                }
            }
        }
        __syncthreads();
    }

    // ---- normalize + write O in [b][s][h*64+d]
#pragma unroll
    for (int mf = 0; mf < 2; mf++) {
        const float il = 1.f / lrow[mf][0], ih = 1.f / lrow[mf][1];
        const int r0 = wrow + mf * 16 + gid;
        const int r1 = r0 + 8;
#pragma unroll
        for (int j = 0; j < 8; j++) {
            const int col = h * 64 + 8 * j + 2 * tig;
            const size_t e0 = ((size_t)(b * S_LEN + r0)) * HID + col;
            const size_t e1 = ((size_t)(b * S_LEN + r1)) * HID + col;
            *(uint32_t*)(Ohi + e0) = packh2(__float2half_rn(oa[mf][j][0] * il),
                                            __float2half_rn(oa[mf][j][1] * il));
            *(uint32_t*)(Ohi + e1) = packh2(__float2half_rn(oa[mf][j][2] * ih),
                                            __float2half_rn(oa[mf][j][3] * ih));
        }
    }
}

// ---------------------------------------------------------------------------
// Launch. Inputs: hidden_state, attention_mask (exact causal tril ->
// analytic, d_in[1] unused), wq,bq,wk,bk,wv,bv,wo,bo.
// ---------------------------------------------------------------------------
extern "C" void kernel_launch(void* const* d_in, const int* in_sizes, int n_in,
                              void* d_out, int out_size)
{
    const float* X  = (const float*)d_in[0];
    const float* wq = (const float*)d_in[2];
    const float* bq = (const float*)d_in[3];
    const float* wk = (const float*)d_in[4];
    const float* bk = (const float*)d_in[5];
    const float* wv = (const float*)d_in[6];
    const float* bv = (const float*)d_in[7];
    const float* wo = (const float*)d_in[8];
    const float* bo = (const float*)d_in[9];
    float* out = (float*)d_out;

    __half *xhi, *whi, *qhi, *khi, *vhi, *ohi;
    cudaGetSymbolAddress((void**)&xhi, g_xhi);
    cudaGetSymbolAddress((void**)&whi, g_whi);
    cudaGetSymbolAddress((void**)&qhi, g_qhi);
    cudaGetSymbolAddress((void**)&khi, g_khi);
    cudaGetSymbolAddress((void**)&vhi, g_vhi);
    cudaGetSymbolAddress((void**)&ohi, g_ohi);

    cudaFuncSetAttribute(gemm_h<0>, cudaFuncAttributeMaxDynamicSharedMemorySize, GEMM_SMEM);
    cudaFuncSetAttribute(gemm_h<1>, cudaFuncAttributeMaxDynamicSharedMemorySize, GEMM_SMEM);
    cudaFuncSetAttribute(flash_mma, cudaFuncAttributeMaxDynamicSharedMemorySize, FLASH_SMEM);

    const int NX4 = M_TOT * HID / 4;
    const int NW4 = HID * HID / 4;

    // fp32 -> fp16 converts
    conv_h<<<NX4 / 256, 256>>>((const float4*)X, (uint32_t*)xhi, NX4);
    dim3 wconv(NW4 / 256, 4);
    conv_w4<<<wconv, 256>>>((const float4*)wq, (const float4*)wk,
                            (const float4*)wv, (const float4*)wo, (uint32_t*)whi);

    // fused QKV projections (1-pass fp16); Q pre-scaled by 0.125*log2(e)
    dim3 qkv_grid(HID / 128, M_TOT / 128, 3);
    gemm_h<0><<<qkv_grid, 256, GEMM_SMEM>>>(xhi, whi, bq, bk, bv,
                                            qhi, khi, vhi, nullptr);

    // attention (Br=128, Bc=64, exp2-domain softmax)
    dim3 agrid(S_LEN / 128, NHEAD, BATCH);
    flash_mma<<<agrid, 128, FLASH_SMEM>>>(qhi, khi, vhi, ohi);

    // output projection (1-pass fp16) -> fp32 out
    dim3 ogrid(HID / 128, M_TOT / 128, 1);
    gemm_h<1><<<ogrid, 256, GEMM_SMEM>>>(ohi, whi + 3 * (size_t)HID * HID,
                                         bo, nullptr, nullptr,
                                         nullptr, nullptr, nullptr, out);
}